// round 9
// baseline (speedup 1.0000x reference)
#include <cuda_runtime.h>
#include <cstdint>

#define NMAX 100000
#define EMAX 1000000
#define HF   64      // hidden features
#define CF   40      // classes
#define CFP  48      // padded classifier cols
#define BM   128
#define BK   16
#define XSTR 132

// Device-only scratch. Never passed from host. Zero-initialized at load;
// g_cnt is re-zeroed by k_scanC_prep each call (deterministic).
__device__ __align__(16) float g_A [(size_t)NMAX * HF];  // layer-1 A' = (x@W1)*dinv
__device__ __align__(16) float g_B [(size_t)NMAX * HF];  // layer-2 A' = (relu(agg1+b1)@W2)*dinv
__device__ __align__(16) float g_dinv[NMAX];
__device__ __align__(16) int   g_cnt[NMAX];
__device__ __align__(16) int   g_rowptr[NMAX + 1];
__device__ __align__(16) int   g_cur[NMAX];
__device__ __align__(16) int   g_col[EMAX];
__device__ __align__(16) int   g_bsum[128];

// ------------------------------------------------------------- CSR build
__global__ void k_count(const int* __restrict__ ei, int E) {
    int e = blockIdx.x * blockDim.x + threadIdx.x;
    if (e < E) atomicAdd(&g_cnt[ei[E + e]], 1);
}
// exclusive scan of g_cnt per 1024-chunk into g_rowptr; chunk sums -> g_bsum
__global__ void k_scanA(int n) {
    __shared__ int sm[256];
    int tid  = threadIdx.x;
    int idx  = blockIdx.x * 1024 + tid * 4;
    int v0 = 0, v1 = 0, v2 = 0, v3 = 0;
    if (idx + 3 < n) {
        int4 t = *reinterpret_cast<const int4*>(&g_cnt[idx]);
        v0 = t.x; v1 = t.y; v2 = t.z; v3 = t.w;
    } else {
        if (idx     < n) v0 = g_cnt[idx];
        if (idx + 1 < n) v1 = g_cnt[idx + 1];
        if (idx + 2 < n) v2 = g_cnt[idx + 2];
        if (idx + 3 < n) v3 = g_cnt[idx + 3];
    }
    sm[tid] = v0 + v1 + v2 + v3;
    __syncthreads();
    for (int off = 1; off < 256; off <<= 1) {
        int t = (tid >= off) ? sm[tid - off] : 0;
        __syncthreads();
        sm[tid] += t;
        __syncthreads();
    }
    int excl = (tid > 0) ? sm[tid - 1] : 0;
    if (tid == 255) g_bsum[blockIdx.x] = sm[255];
    if (idx     < n) g_rowptr[idx]     = excl;
    if (idx + 1 < n) g_rowptr[idx + 1] = excl + v0;
    if (idx + 2 < n) g_rowptr[idx + 2] = excl + v0 + v1;
    if (idx + 3 < n) g_rowptr[idx + 3] = excl + v0 + v1 + v2;
}
// per-block redundant scan of chunk sums + rowptr fixup + cursors + dinv + cnt reset
__global__ void k_scanC_prep(int N, int E, int nb) {
    __shared__ int sb[128];
    int tid = threadIdx.x;
    if (tid < 128) sb[tid] = (tid < nb) ? g_bsum[tid] : 0;
    __syncthreads();
    for (int off = 1; off < 128; off <<= 1) {
        int t = (tid < 128 && tid >= off) ? sb[tid - off] : 0;
        __syncthreads();
        if (tid < 128) sb[tid] += t;
        __syncthreads();
    }
    int i = blockIdx.x * blockDim.x + tid;
    if (i < N) {
        int blk = i >> 10;
        int off = (blk > 0) ? sb[blk - 1] : 0;
        int rp = g_rowptr[i] + off;
        g_rowptr[i] = rp;
        g_cur[i]    = rp;
        g_dinv[i]   = rsqrtf((float)(g_cnt[i] + 1));   // +1 self loop
        g_cnt[i]    = 0;                               // ready for next call
    }
    if (i == 0) g_rowptr[N] = E;
}
__global__ void k_fill(const int* __restrict__ ei, int E) {
    int e = blockIdx.x * blockDim.x + threadIdx.x;
    if (e < E) {
        int s = ei[e];
        int d = ei[E + e];
        int pos = atomicAdd(&g_cur[d], 1);
        g_col[pos] = s;
    }
}

// ------------------------------------------------------------ gather helper
// returns dinv[d] * ( A'[d,:] + sum_{j in row d} A'[col[j],:] )  (float4 slice sub)
__device__ __forceinline__ float4 gather_row(const float4* __restrict__ Ap,
                                             int d, int sub) {
    int beg = __ldg(&g_rowptr[d]);
    int end = __ldg(&g_rowptr[d + 1]);
    float4 acc = Ap[(size_t)d * 16 + sub];
    int j = beg;
    for (; j + 1 < end; j += 2) {
        int s0 = __ldg(&g_col[j]);
        int s1 = __ldg(&g_col[j + 1]);
        float4 v0 = Ap[(size_t)s0 * 16 + sub];
        float4 v1 = Ap[(size_t)s1 * 16 + sub];
        acc.x += v0.x + v1.x;
        acc.y += v0.y + v1.y;
        acc.z += v0.z + v1.z;
        acc.w += v0.w + v1.w;
    }
    if (j < end) {
        int s = __ldg(&g_col[j]);
        float4 v = Ap[(size_t)s * 16 + sub];
        acc.x += v.x; acc.y += v.y; acc.z += v.z; acc.w += v.w;
    }
    float di = g_dinv[d];
    acc.x *= di; acc.y *= di; acc.z *= di; acc.w *= di;
    return acc;
}

// ------------------------------------------------------- GEMM1 (K=128, from gmem X)
// g_A[row] = (x[row] @ W1) * dinv[row]
__global__ void __launch_bounds__(256)
k_gemm1(const float* __restrict__ X, const float* __restrict__ W, int N) {
    __shared__ float Ws[128 * HF];
    __shared__ float Xs[BK * XSTR];

    const int tid = threadIdx.x;
    {
        const float4* Wv = reinterpret_cast<const float4*>(W);
        float4* Wsv = reinterpret_cast<float4*>(Ws);
        for (int i = tid; i < 128 * HF / 4; i += 256) Wsv[i] = Wv[i];
    }
    const int bm = blockIdx.x * BM;
    const int tc = tid & 15;
    const int tr = tid >> 4;

    float acc[8][4];
#pragma unroll
    for (int i = 0; i < 8; i++)
#pragma unroll
        for (int j = 0; j < 4; j++) acc[i][j] = 0.0f;

    __syncthreads();

    for (int k0 = 0; k0 < 128; k0 += BK) {
#pragma unroll
        for (int i = tid; i < BM * BK / 4; i += 256) {
            int row = i >> 2;
            int kq  = i & 3;
            int r   = bm + row;
            float4 v = make_float4(0.f, 0.f, 0.f, 0.f);
            if (r < N)
                v = *reinterpret_cast<const float4*>(X + (size_t)r * 128 + k0 + kq * 4);
            Xs[(kq * 4 + 0) * XSTR + row] = v.x;
            Xs[(kq * 4 + 1) * XSTR + row] = v.y;
            Xs[(kq * 4 + 2) * XSTR + row] = v.z;
            Xs[(kq * 4 + 3) * XSTR + row] = v.w;
        }
        __syncthreads();

#pragma unroll
        for (int kk = 0; kk < BK; kk++) {
            float4 xa = *reinterpret_cast<const float4*>(&Xs[kk * XSTR + tr * 8 + 0]);
            float4 xb = *reinterpret_cast<const float4*>(&Xs[kk * XSTR + tr * 8 + 4]);
            float4 wv = *reinterpret_cast<const float4*>(&Ws[(k0 + kk) * HF + tc * 4]);
            float xr[8] = {xa.x, xa.y, xa.z, xa.w, xb.x, xb.y, xb.z, xb.w};
#pragma unroll
            for (int i = 0; i < 8; i++) {
                acc[i][0] += xr[i] * wv.x;
                acc[i][1] += xr[i] * wv.y;
                acc[i][2] += xr[i] * wv.z;
                acc[i][3] += xr[i] * wv.w;
            }
        }
        __syncthreads();
    }

#pragma unroll
    for (int i = 0; i < 8; i++) {
        int r = bm + tr * 8 + i;
        if (r >= N) break;
        float di = g_dinv[r];
        float4 v = make_float4(acc[i][0] * di, acc[i][1] * di,
                               acc[i][2] * di, acc[i][3] * di);
        *reinterpret_cast<float4*>(g_A + (size_t)r * HF + tc * 4) = v;
    }
}

// --------------------------------- GEMM2 fused with gather (dynamic smem 50KB)
// g_B[row] = ( relu( gather(g_A)[row] + b1 ) @ W2 ) * dinv[row]
__global__ void __launch_bounds__(256)
k_gemm2_fused(const float* __restrict__ W, const float* __restrict__ bias, int N) {
    extern __shared__ float smem[];
    float* Ws = smem;                 // 64*64
    float* Xs = smem + HF * HF;       // 64*XSTR, transposed [k][row]

    const int tid = threadIdx.x;
    {
        const float4* Wv = reinterpret_cast<const float4*>(W);
        float4* Wsv = reinterpret_cast<float4*>(Ws);
        for (int i = tid; i < HF * HF / 4; i += 256) Wsv[i] = Wv[i];
    }

    const int bm  = blockIdx.x * BM;
    const int hw  = tid >> 4;          // half-warp id 0..15
    const int sub = tid & 15;          // float4 slice within row

    const float4* Ap = reinterpret_cast<const float4*>(g_A);
    float4 bv = *reinterpret_cast<const float4*>(bias + sub * 4);

    for (int row = hw; row < BM; row += 16) {
        int d = bm + row;
        float4 xv = make_float4(0.f, 0.f, 0.f, 0.f);
        if (d < N) {
            float4 a = gather_row(Ap, d, sub);
            xv.x = fmaxf(a.x + bv.x, 0.0f);
            xv.y = fmaxf(a.y + bv.y, 0.0f);
            xv.z = fmaxf(a.z + bv.z, 0.0f);
            xv.w = fmaxf(a.w + bv.w, 0.0f);
        }
        Xs[(sub * 4 + 0) * XSTR + row] = xv.x;
        Xs[(sub * 4 + 1) * XSTR + row] = xv.y;
        Xs[(sub * 4 + 2) * XSTR + row] = xv.z;
        Xs[(sub * 4 + 3) * XSTR + row] = xv.w;
    }
    __syncthreads();

    const int tc = tid & 15;
    const int tr = tid >> 4;
    float acc[8][4];
#pragma unroll
    for (int i = 0; i < 8; i++)
#pragma unroll
        for (int j = 0; j < 4; j++) acc[i][j] = 0.0f;

#pragma unroll 8
    for (int kk = 0; kk < HF; kk++) {
        float4 xa = *reinterpret_cast<const float4*>(&Xs[kk * XSTR + tr * 8 + 0]);
        float4 xb = *reinterpret_cast<const float4*>(&Xs[kk * XSTR + tr * 8 + 4]);
        float4 wv = *reinterpret_cast<const float4*>(&Ws[kk * HF + tc * 4]);
        float xr[8] = {xa.x, xa.y, xa.z, xa.w, xb.x, xb.y, xb.z, xb.w};
#pragma unroll
        for (int i = 0; i < 8; i++) {
            acc[i][0] += xr[i] * wv.x;
            acc[i][1] += xr[i] * wv.y;
            acc[i][2] += xr[i] * wv.z;
            acc[i][3] += xr[i] * wv.w;
        }
    }

#pragma unroll
    for (int i = 0; i < 8; i++) {
        int r = bm + tr * 8 + i;
        if (r >= N) break;
        float di = g_dinv[r];
        float4 v = make_float4(acc[i][0] * di, acc[i][1] * di,
                               acc[i][2] * di, acc[i][3] * di);
        *reinterpret_cast<float4*>(g_B + (size_t)r * HF + tc * 4) = v;
    }
}

// --------------------------- classifier fused with gather (static smem ~46.5KB)
// out[row] = relu( gather(g_B)[row] + b2 ) @ Wc + bc
__global__ void __launch_bounds__(192)
k_final_fused(const float* __restrict__ b2, const float* __restrict__ Wc,
              const float* __restrict__ bc, float* __restrict__ out, int N) {
    __shared__ float Ws[HF * CFP];     // 64 x 48 zero-padded
    __shared__ float Xs[HF * XSTR];    // transposed [k][row]
    __shared__ float bcs[CFP];

    const int tid = threadIdx.x;
    for (int i = tid; i < HF * CFP; i += 192) {
        int k = i / CFP, c = i % CFP;
        Ws[i] = (c < CF) ? Wc[k * CF + c] : 0.0f;
    }
    if (tid < CFP) bcs[tid] = (tid < CF) ? bc[tid] : 0.0f;

    const int bm  = blockIdx.x * BM;
    const int hw  = tid >> 4;          // 0..11
    const int sub = tid & 15;

    const float4* Ap = reinterpret_cast<const float4*>(g_B);
    float4 bv = *reinterpret_cast<const float4*>(b2 + sub * 4);

    for (int row = hw; row < BM; row += 12) {
        int d = bm + row;
        float4 xv = make_float4(0.f, 0.f, 0.f, 0.f);
        if (d < N) {
            float4 a = gather_row(Ap, d, sub);
            xv.x = fmaxf(a.x + bv.x, 0.0f);
            xv.y = fmaxf(a.y + bv.y, 0.0f);
            xv.z = fmaxf(a.z + bv.z, 0.0f);
            xv.w = fmaxf(a.w + bv.w, 0.0f);
        }
        Xs[(sub * 4 + 0) * XSTR + row] = xv.x;
        Xs[(sub * 4 + 1) * XSTR + row] = xv.y;
        Xs[(sub * 4 + 2) * XSTR + row] = xv.z;
        Xs[(sub * 4 + 3) * XSTR + row] = xv.w;
    }
    __syncthreads();

    const int tc = tid % 12;
    const int tr = tid / 12;
    float acc[8][4];
#pragma unroll
    for (int i = 0; i < 8; i++)
#pragma unroll
        for (int j = 0; j < 4; j++) acc[i][j] = 0.0f;

#pragma unroll 8
    for (int kk = 0; kk < HF; kk++) {
        float4 xa = *reinterpret_cast<const float4*>(&Xs[kk * XSTR + tr * 8 + 0]);
        float4 xb = *reinterpret_cast<const float4*>(&Xs[kk * XSTR + tr * 8 + 4]);
        float4 wv = *reinterpret_cast<const float4*>(&Ws[kk * CFP + tc * 4]);
        float xr[8] = {xa.x, xa.y, xa.z, xa.w, xb.x, xb.y, xb.z, xb.w};
#pragma unroll
        for (int i = 0; i < 8; i++) {
            acc[i][0] += xr[i] * wv.x;
            acc[i][1] += xr[i] * wv.y;
            acc[i][2] += xr[i] * wv.z;
            acc[i][3] += xr[i] * wv.w;
        }
    }

    if (tc * 4 < CF) {
#pragma unroll
        for (int i = 0; i < 8; i++) {
            int r = bm + tr * 8 + i;
            if (r >= N) break;
            float4 v = make_float4(acc[i][0] + bcs[tc * 4 + 0],
                                   acc[i][1] + bcs[tc * 4 + 1],
                                   acc[i][2] + bcs[tc * 4 + 2],
                                   acc[i][3] + bcs[tc * 4 + 3]);
            *reinterpret_cast<float4*>(out + (size_t)r * CF + tc * 4) = v;
        }
    }
}

// ------------------------------------------------------------------ launcher
extern "C" void kernel_launch(void* const* d_in, const int* in_sizes, int n_in,
                              void* d_out, int out_size) {
    const float* x  = (const float*)d_in[0];
    const int*   ei = (const int*)d_in[1];     // int32 (JAX x64-disabled)
    const float* W1 = (const float*)d_in[2];
    const float* b1 = (const float*)d_in[3];
    const float* W2 = (const float*)d_in[4];
    const float* b2 = (const float*)d_in[5];
    const float* Wc = (const float*)d_in[6];
    const float* bc = (const float*)d_in[7];
    float*       out = (float*)d_out;

    const int Hdim = in_sizes[3];             // 64
    const int Fin  = in_sizes[2] / Hdim;      // 128
    const int N    = in_sizes[0] / Fin;       // 100000
    const int E    = in_sizes[1] / 2;         // 1000000
    (void)Hdim; (void)n_in; (void)out_size;

    const int TPB = 256;
    int nBlk  = (N + TPB - 1) / TPB;
    int eBlk  = (E + TPB - 1) / TPB;
    int gBlk  = (N + BM - 1) / BM;
    int sBlkA = (N + 1023) / 1024;            // 98

    static bool attr_set = false;
    const int dynSmem = (HF * HF + HF * XSTR) * (int)sizeof(float);  // ~50.2KB
    if (!attr_set) {
        cudaFuncSetAttribute(k_gemm2_fused,
                             cudaFuncAttributeMaxDynamicSharedMemorySize, dynSmem);
        attr_set = true;
    }

    // CSR build (4 launches; g_cnt arrives zeroed, leaves zeroed)
    k_count<<<eBlk, TPB>>>(ei, E);
    k_scanA<<<sBlkA, 256>>>(N);
    k_scanC_prep<<<nBlk, TPB>>>(N, E, sBlkA);
    k_fill<<<eBlk, TPB>>>(ei, E);

    // layer 1: A' = (x@W1)*dinv
    k_gemm1<<<gBlk, TPB>>>(x, W1, N);
    // layer 2 fused: B' = (relu(gather(A')+b1)@W2)*dinv
    k_gemm2_fused<<<gBlk, TPB, dynSmem>>>(W2, b1, N);
    // classifier fused: out = relu(gather(B')+b2)@Wc + bc
    k_final_fused<<<gBlk, 192>>>(b2, Wc, bc, out, N);
}

// round 10
// speedup vs baseline: 1.0484x; 1.0484x over previous
#include <cuda_runtime.h>
#include <cstdint>

#define NMAX 100000
#define EMAX 1000000
#define HF   64      // hidden features
#define CF   40      // classes
#define CFP  48      // padded classifier cols
#define BM   128
#define BK   16
#define XSTR 132

// Device-only scratch. Never passed from host. Zero-initialized at load;
// g_cnt is re-zeroed by k_scanC_prep each call (deterministic).
__device__ __align__(16) float g_A [(size_t)NMAX * HF];  // layer-1 A' = (x@W1)*dinv
__device__ __align__(16) float g_B [(size_t)NMAX * HF];  // layer-2 A' = (relu(agg1+b1)@W2)*dinv
__device__ __align__(16) float g_dinv[NMAX];
__device__ __align__(16) int   g_cnt[NMAX];
__device__ __align__(16) int   g_rowptr[NMAX + 1];
__device__ __align__(16) int   g_cur[NMAX];
__device__ __align__(16) int   g_col[EMAX];
__device__ __align__(16) int   g_bsum[128];

// ------------------------------------------------------------- CSR build
__global__ void k_count(const int* __restrict__ ei, int E) {
    int e = blockIdx.x * blockDim.x + threadIdx.x;
    if (e < E) atomicAdd(&g_cnt[ei[E + e]], 1);
}
// exclusive scan of g_cnt per 1024-chunk into g_rowptr; chunk sums -> g_bsum
__global__ void k_scanA(int n) {
    __shared__ int sm[256];
    int tid  = threadIdx.x;
    int idx  = blockIdx.x * 1024 + tid * 4;
    int v0 = 0, v1 = 0, v2 = 0, v3 = 0;
    if (idx + 3 < n) {
        int4 t = *reinterpret_cast<const int4*>(&g_cnt[idx]);
        v0 = t.x; v1 = t.y; v2 = t.z; v3 = t.w;
    } else {
        if (idx     < n) v0 = g_cnt[idx];
        if (idx + 1 < n) v1 = g_cnt[idx + 1];
        if (idx + 2 < n) v2 = g_cnt[idx + 2];
        if (idx + 3 < n) v3 = g_cnt[idx + 3];
    }
    sm[tid] = v0 + v1 + v2 + v3;
    __syncthreads();
    for (int off = 1; off < 256; off <<= 1) {
        int t = (tid >= off) ? sm[tid - off] : 0;
        __syncthreads();
        sm[tid] += t;
        __syncthreads();
    }
    int excl = (tid > 0) ? sm[tid - 1] : 0;
    if (tid == 255) g_bsum[blockIdx.x] = sm[255];
    if (idx     < n) g_rowptr[idx]     = excl;
    if (idx + 1 < n) g_rowptr[idx + 1] = excl + v0;
    if (idx + 2 < n) g_rowptr[idx + 2] = excl + v0 + v1;
    if (idx + 3 < n) g_rowptr[idx + 3] = excl + v0 + v1 + v2;
}
// per-block redundant scan of chunk sums + rowptr fixup + cursors + dinv + cnt reset
__global__ void k_scanC_prep(int N, int E, int nb) {
    __shared__ int sb[128];
    int tid = threadIdx.x;
    if (tid < 128) sb[tid] = (tid < nb) ? g_bsum[tid] : 0;
    __syncthreads();
    for (int off = 1; off < 128; off <<= 1) {
        int t = (tid < 128 && tid >= off) ? sb[tid - off] : 0;
        __syncthreads();
        if (tid < 128) sb[tid] += t;
        __syncthreads();
    }
    int i = blockIdx.x * blockDim.x + tid;
    if (i < N) {
        int blk = i >> 10;
        int off = (blk > 0) ? sb[blk - 1] : 0;
        int rp = g_rowptr[i] + off;
        g_rowptr[i] = rp;
        g_cur[i]    = rp;
        g_dinv[i]   = rsqrtf((float)(g_cnt[i] + 1));   // +1 self loop
        g_cnt[i]    = 0;                               // ready for next call
    }
    if (i == 0) g_rowptr[N] = E;
}
__global__ void k_fill(const int* __restrict__ ei, int E) {
    int e = blockIdx.x * blockDim.x + threadIdx.x;
    if (e < E) {
        int s = ei[e];
        int d = ei[E + e];
        int pos = atomicAdd(&g_cur[d], 1);
        g_col[pos] = s;
    }
}

// ------------------------------------------------------------ gather helper
// returns dinv[d] * ( A'[d,:] + sum_{j in row d} A'[col[j],:] )  (float4 slice sub)
__device__ __forceinline__ float4 gather_row(const float4* __restrict__ Ap,
                                             int d, int sub) {
    int beg = __ldg(&g_rowptr[d]);
    int end = __ldg(&g_rowptr[d + 1]);
    float4 acc = Ap[(size_t)d * 16 + sub];
    int j = beg;
    for (; j + 1 < end; j += 2) {
        int s0 = __ldg(&g_col[j]);
        int s1 = __ldg(&g_col[j + 1]);
        float4 v0 = Ap[(size_t)s0 * 16 + sub];
        float4 v1 = Ap[(size_t)s1 * 16 + sub];
        acc.x += v0.x + v1.x;
        acc.y += v0.y + v1.y;
        acc.z += v0.z + v1.z;
        acc.w += v0.w + v1.w;
    }
    if (j < end) {
        int s = __ldg(&g_col[j]);
        float4 v = Ap[(size_t)s * 16 + sub];
        acc.x += v.x; acc.y += v.y; acc.z += v.z; acc.w += v.w;
    }
    float di = g_dinv[d];
    acc.x *= di; acc.y *= di; acc.z *= di; acc.w *= di;
    return acc;
}

// ------------------------------------------------------- GEMM1 (K=128, from gmem X)
// g_A[row] = (x[row] @ W1) * dinv[row]
__global__ void __launch_bounds__(256)
k_gemm1(const float* __restrict__ X, const float* __restrict__ W, int N) {
    __shared__ float Ws[128 * HF];
    __shared__ float Xs[BK * XSTR];

    const int tid = threadIdx.x;
    {
        const float4* Wv = reinterpret_cast<const float4*>(W);
        float4* Wsv = reinterpret_cast<float4*>(Ws);
        for (int i = tid; i < 128 * HF / 4; i += 256) Wsv[i] = Wv[i];
    }
    const int bm = blockIdx.x * BM;
    const int tc = tid & 15;
    const int tr = tid >> 4;

    float acc[8][4];
#pragma unroll
    for (int i = 0; i < 8; i++)
#pragma unroll
        for (int j = 0; j < 4; j++) acc[i][j] = 0.0f;

    __syncthreads();

    for (int k0 = 0; k0 < 128; k0 += BK) {
#pragma unroll
        for (int i = tid; i < BM * BK / 4; i += 256) {
            int row = i >> 2;
            int kq  = i & 3;
            int r   = bm + row;
            float4 v = make_float4(0.f, 0.f, 0.f, 0.f);
            if (r < N)
                v = *reinterpret_cast<const float4*>(X + (size_t)r * 128 + k0 + kq * 4);
            Xs[(kq * 4 + 0) * XSTR + row] = v.x;
            Xs[(kq * 4 + 1) * XSTR + row] = v.y;
            Xs[(kq * 4 + 2) * XSTR + row] = v.z;
            Xs[(kq * 4 + 3) * XSTR + row] = v.w;
        }
        __syncthreads();

#pragma unroll
        for (int kk = 0; kk < BK; kk++) {
            float4 xa = *reinterpret_cast<const float4*>(&Xs[kk * XSTR + tr * 8 + 0]);
            float4 xb = *reinterpret_cast<const float4*>(&Xs[kk * XSTR + tr * 8 + 4]);
            float4 wv = *reinterpret_cast<const float4*>(&Ws[(k0 + kk) * HF + tc * 4]);
            float xr[8] = {xa.x, xa.y, xa.z, xa.w, xb.x, xb.y, xb.z, xb.w};
#pragma unroll
            for (int i = 0; i < 8; i++) {
                acc[i][0] += xr[i] * wv.x;
                acc[i][1] += xr[i] * wv.y;
                acc[i][2] += xr[i] * wv.z;
                acc[i][3] += xr[i] * wv.w;
            }
        }
        __syncthreads();
    }

#pragma unroll
    for (int i = 0; i < 8; i++) {
        int r = bm + tr * 8 + i;
        if (r >= N) break;
        float di = g_dinv[r];
        float4 v = make_float4(acc[i][0] * di, acc[i][1] * di,
                               acc[i][2] * di, acc[i][3] * di);
        *reinterpret_cast<float4*>(g_A + (size_t)r * HF + tc * 4) = v;
    }
}

// --------------------------------- GEMM2 fused with gather (dynamic smem 50KB)
// g_B[row] = ( relu( gather(g_A)[row] + b1 ) @ W2 ) * dinv[row]
__global__ void __launch_bounds__(256)
k_gemm2_fused(const float* __restrict__ W, const float* __restrict__ bias, int N) {
    extern __shared__ float smem[];
    float* Ws = smem;                 // 64*64
    float* Xs = smem + HF * HF;       // 64*XSTR, transposed [k][row]

    const int tid = threadIdx.x;
    {
        const float4* Wv = reinterpret_cast<const float4*>(W);
        float4* Wsv = reinterpret_cast<float4*>(Ws);
        for (int i = tid; i < HF * HF / 4; i += 256) Wsv[i] = Wv[i];
    }

    const int bm  = blockIdx.x * BM;
    const int hw  = tid >> 4;          // half-warp id 0..15
    const int sub = tid & 15;          // float4 slice within row

    const float4* Ap = reinterpret_cast<const float4*>(g_A);
    float4 bv = *reinterpret_cast<const float4*>(bias + sub * 4);

    for (int row = hw; row < BM; row += 16) {
        int d = bm + row;
        float4 xv = make_float4(0.f, 0.f, 0.f, 0.f);
        if (d < N) {
            float4 a = gather_row(Ap, d, sub);
            xv.x = fmaxf(a.x + bv.x, 0.0f);
            xv.y = fmaxf(a.y + bv.y, 0.0f);
            xv.z = fmaxf(a.z + bv.z, 0.0f);
            xv.w = fmaxf(a.w + bv.w, 0.0f);
        }
        Xs[(sub * 4 + 0) * XSTR + row] = xv.x;
        Xs[(sub * 4 + 1) * XSTR + row] = xv.y;
        Xs[(sub * 4 + 2) * XSTR + row] = xv.z;
        Xs[(sub * 4 + 3) * XSTR + row] = xv.w;
    }
    __syncthreads();

    const int tc = tid & 15;
    const int tr = tid >> 4;
    float acc[8][4];
#pragma unroll
    for (int i = 0; i < 8; i++)
#pragma unroll
        for (int j = 0; j < 4; j++) acc[i][j] = 0.0f;

#pragma unroll 8
    for (int kk = 0; kk < HF; kk++) {
        float4 xa = *reinterpret_cast<const float4*>(&Xs[kk * XSTR + tr * 8 + 0]);
        float4 xb = *reinterpret_cast<const float4*>(&Xs[kk * XSTR + tr * 8 + 4]);
        float4 wv = *reinterpret_cast<const float4*>(&Ws[kk * HF + tc * 4]);
        float xr[8] = {xa.x, xa.y, xa.z, xa.w, xb.x, xb.y, xb.z, xb.w};
#pragma unroll
        for (int i = 0; i < 8; i++) {
            acc[i][0] += xr[i] * wv.x;
            acc[i][1] += xr[i] * wv.y;
            acc[i][2] += xr[i] * wv.z;
            acc[i][3] += xr[i] * wv.w;
        }
    }

#pragma unroll
    for (int i = 0; i < 8; i++) {
        int r = bm + tr * 8 + i;
        if (r >= N) break;
        float di = g_dinv[r];
        float4 v = make_float4(acc[i][0] * di, acc[i][1] * di,
                               acc[i][2] * di, acc[i][3] * di);
        *reinterpret_cast<float4*>(g_B + (size_t)r * HF + tc * 4) = v;
    }
}

// --------------------------- classifier fused with gather (static smem ~46.5KB)
// out[row] = relu( gather(g_B)[row] + b2 ) @ Wc + bc
__global__ void __launch_bounds__(192)
k_final_fused(const float* __restrict__ b2, const float* __restrict__ Wc,
              const float* __restrict__ bc, float* __restrict__ out, int N) {
    __shared__ float Ws[HF * CFP];     // 64 x 48 zero-padded
    __shared__ float Xs[HF * XSTR];    // transposed [k][row]
    __shared__ float bcs[CFP];

    const int tid = threadIdx.x;
    for (int i = tid; i < HF * CFP; i += 192) {
        int k = i / CFP, c = i % CFP;
        Ws[i] = (c < CF) ? Wc[k * CF + c] : 0.0f;
    }
    if (tid < CFP) bcs[tid] = (tid < CF) ? bc[tid] : 0.0f;

    const int bm  = blockIdx.x * BM;
    const int hw  = tid >> 4;          // 0..11
    const int sub = tid & 15;

    const float4* Ap = reinterpret_cast<const float4*>(g_B);
    float4 bv = *reinterpret_cast<const float4*>(b2 + sub * 4);

    for (int row = hw; row < BM; row += 12) {
        int d = bm + row;
        float4 xv = make_float4(0.f, 0.f, 0.f, 0.f);
        if (d < N) {
            float4 a = gather_row(Ap, d, sub);
            xv.x = fmaxf(a.x + bv.x, 0.0f);
            xv.y = fmaxf(a.y + bv.y, 0.0f);
            xv.z = fmaxf(a.z + bv.z, 0.0f);
            xv.w = fmaxf(a.w + bv.w, 0.0f);
        }
        Xs[(sub * 4 + 0) * XSTR + row] = xv.x;
        Xs[(sub * 4 + 1) * XSTR + row] = xv.y;
        Xs[(sub * 4 + 2) * XSTR + row] = xv.z;
        Xs[(sub * 4 + 3) * XSTR + row] = xv.w;
    }
    __syncthreads();

    const int tc = tid % 12;
    const int tr = tid / 12;
    float acc[8][4];
#pragma unroll
    for (int i = 0; i < 8; i++)
#pragma unroll
        for (int j = 0; j < 4; j++) acc[i][j] = 0.0f;

#pragma unroll 8
    for (int kk = 0; kk < HF; kk++) {
        float4 xa = *reinterpret_cast<const float4*>(&Xs[kk * XSTR + tr * 8 + 0]);
        float4 xb = *reinterpret_cast<const float4*>(&Xs[kk * XSTR + tr * 8 + 4]);
        float4 wv = *reinterpret_cast<const float4*>(&Ws[kk * CFP + tc * 4]);
        float xr[8] = {xa.x, xa.y, xa.z, xa.w, xb.x, xb.y, xb.z, xb.w};
#pragma unroll
        for (int i = 0; i < 8; i++) {
            acc[i][0] += xr[i] * wv.x;
            acc[i][1] += xr[i] * wv.y;
            acc[i][2] += xr[i] * wv.z;
            acc[i][3] += xr[i] * wv.w;
        }
    }

    if (tc * 4 < CF) {
#pragma unroll
        for (int i = 0; i < 8; i++) {
            int r = bm + tr * 8 + i;
            if (r >= N) break;
            float4 v = make_float4(acc[i][0] + bcs[tc * 4 + 0],
                                   acc[i][1] + bcs[tc * 4 + 1],
                                   acc[i][2] + bcs[tc * 4 + 2],
                                   acc[i][3] + bcs[tc * 4 + 3]);
            *reinterpret_cast<float4*>(out + (size_t)r * CF + tc * 4) = v;
        }
    }
}

// ------------------------------------------------------------------ launcher
extern "C" void kernel_launch(void* const* d_in, const int* in_sizes, int n_in,
                              void* d_out, int out_size) {
    const float* x  = (const float*)d_in[0];
    const int*   ei = (const int*)d_in[1];     // int32 (JAX x64-disabled)
    const float* W1 = (const float*)d_in[2];
    const float* b1 = (const float*)d_in[3];
    const float* W2 = (const float*)d_in[4];
    const float* b2 = (const float*)d_in[5];
    const float* Wc = (const float*)d_in[6];
    const float* bc = (const float*)d_in[7];
    float*       out = (float*)d_out;

    const int Hdim = in_sizes[3];             // 64
    const int Fin  = in_sizes[2] / Hdim;      // 128
    const int N    = in_sizes[0] / Fin;       // 100000
    const int E    = in_sizes[1] / 2;         // 1000000
    (void)Hdim; (void)n_in; (void)out_size;

    const int TPB = 256;
    int nBlk  = (N + TPB - 1) / TPB;
    int eBlk  = (E + TPB - 1) / TPB;
    int gBlk  = (N + BM - 1) / BM;
    int sBlkA = (N + 1023) / 1024;            // 98

    static bool attr_set = false;
    const int dynSmem = (HF * HF + HF * XSTR) * (int)sizeof(float);  // ~50.2KB
    if (!attr_set) {
        cudaFuncSetAttribute(k_gemm2_fused,
                             cudaFuncAttributeMaxDynamicSharedMemorySize, dynSmem);
        attr_set = true;
    }

    // CSR build (4 launches; g_cnt arrives zeroed, leaves zeroed)
    k_count<<<eBlk, TPB>>>(ei, E);
    k_scanA<<<sBlkA, 256>>>(N);
    k_scanC_prep<<<nBlk, TPB>>>(N, E, sBlkA);
    k_fill<<<eBlk, TPB>>>(ei, E);

    // layer 1: A' = (x@W1)*dinv
    k_gemm1<<<gBlk, TPB>>>(x, W1, N);
    // layer 2 fused: B' = (relu(gather(A')+b1)@W2)*dinv
    k_gemm2_fused<<<gBlk, TPB, dynSmem>>>(W2, b1, N);
    // classifier fused: out = relu(gather(B')+b2)@Wc + bc
    k_final_fused<<<gBlk, 192>>>(b2, Wc, bc, out, N);
}

// round 11
// speedup vs baseline: 1.1396x; 1.0869x over previous
#include <cuda_runtime.h>
#include <cstdint>

#define NMAX 100000
#define EMAX 1000000
#define HF   64      // hidden features
#define CF   40      // classes
#define CFP  48      // padded classifier cols
#define BM   128
#define BK   16
#define XSTR 132

// Device-only scratch. Never passed from host. Zero-initialized at load;
// g_cnt is re-zeroed by k_scanC_prep each call (deterministic).
__device__ __align__(16) float g_A [(size_t)NMAX * HF];  // A' = (in@W) * dinv[row]
__device__ __align__(16) float g_B [(size_t)NMAX * HF];  // aggregation output
__device__ __align__(16) float g_dinv[NMAX];
__device__ __align__(16) int   g_cnt[NMAX];
__device__ __align__(16) int   g_rowptr[NMAX + 1];
__device__ __align__(16) int   g_cur[NMAX];
__device__ __align__(16) int   g_col[EMAX];
__device__ __align__(16) int   g_bsum[128];

// ------------------------------------------------------------- CSR build
// 4 edges per thread (int4) -> MLP=4 on the atomic chains.
__global__ void k_count(const int* __restrict__ ei, int E) {
    int e = (blockIdx.x * blockDim.x + threadIdx.x) * 4;
    if (e + 3 < E) {
        int4 d = *reinterpret_cast<const int4*>(ei + E + e);
        atomicAdd(&g_cnt[d.x], 1);
        atomicAdd(&g_cnt[d.y], 1);
        atomicAdd(&g_cnt[d.z], 1);
        atomicAdd(&g_cnt[d.w], 1);
    } else {
        for (int k = e; k < E; k++) atomicAdd(&g_cnt[ei[E + k]], 1);
    }
}
// exclusive scan of g_cnt per 1024-chunk into g_rowptr; chunk sums -> g_bsum
__global__ void k_scanA(int n) {
    __shared__ int sm[256];
    int tid  = threadIdx.x;
    int idx  = blockIdx.x * 1024 + tid * 4;
    int v0 = 0, v1 = 0, v2 = 0, v3 = 0;
    if (idx + 3 < n) {
        int4 t = *reinterpret_cast<const int4*>(&g_cnt[idx]);
        v0 = t.x; v1 = t.y; v2 = t.z; v3 = t.w;
    } else {
        if (idx     < n) v0 = g_cnt[idx];
        if (idx + 1 < n) v1 = g_cnt[idx + 1];
        if (idx + 2 < n) v2 = g_cnt[idx + 2];
        if (idx + 3 < n) v3 = g_cnt[idx + 3];
    }
    sm[tid] = v0 + v1 + v2 + v3;
    __syncthreads();
    for (int off = 1; off < 256; off <<= 1) {
        int t = (tid >= off) ? sm[tid - off] : 0;
        __syncthreads();
        sm[tid] += t;
        __syncthreads();
    }
    int excl = (tid > 0) ? sm[tid - 1] : 0;
    if (tid == 255) g_bsum[blockIdx.x] = sm[255];
    if (idx     < n) g_rowptr[idx]     = excl;
    if (idx + 1 < n) g_rowptr[idx + 1] = excl + v0;
    if (idx + 2 < n) g_rowptr[idx + 2] = excl + v0 + v1;
    if (idx + 3 < n) g_rowptr[idx + 3] = excl + v0 + v1 + v2;
}
// per-block redundant scan of chunk sums + rowptr fixup + cursors + dinv + cnt reset
__global__ void k_scanC_prep(int N, int E, int nb) {
    __shared__ int sb[128];
    int tid = threadIdx.x;
    if (tid < 128) sb[tid] = (tid < nb) ? g_bsum[tid] : 0;
    __syncthreads();
    for (int off = 1; off < 128; off <<= 1) {
        int t = (tid < 128 && tid >= off) ? sb[tid - off] : 0;
        __syncthreads();
        if (tid < 128) sb[tid] += t;
        __syncthreads();
    }
    int i = blockIdx.x * blockDim.x + tid;
    if (i < N) {
        int blk = i >> 10;
        int off = (blk > 0) ? sb[blk - 1] : 0;
        int rp = g_rowptr[i] + off;
        g_rowptr[i] = rp;
        g_cur[i]    = rp;
        g_dinv[i]   = rsqrtf((float)(g_cnt[i] + 1));   // +1 self loop
        g_cnt[i]    = 0;                               // ready for next call
    }
    if (i == 0) g_rowptr[N] = E;
}
// 4 edges per thread -> 4 independent atomic/store chains.
__global__ void k_fill(const int* __restrict__ ei, int E) {
    int e = (blockIdx.x * blockDim.x + threadIdx.x) * 4;
    if (e + 3 < E) {
        int4 s = *reinterpret_cast<const int4*>(ei + e);
        int4 d = *reinterpret_cast<const int4*>(ei + E + e);
        int p0 = atomicAdd(&g_cur[d.x], 1);
        int p1 = atomicAdd(&g_cur[d.y], 1);
        int p2 = atomicAdd(&g_cur[d.z], 1);
        int p3 = atomicAdd(&g_cur[d.w], 1);
        g_col[p0] = s.x;
        g_col[p1] = s.y;
        g_col[p2] = s.z;
        g_col[p3] = s.w;
    } else {
        for (int k = e; k < E; k++) {
            int pos = atomicAdd(&g_cur[ei[E + k]], 1);
            g_col[pos] = ei[k];
        }
    }
}

// ------------------------------------------------------- tiled GEMM (2D reg-blocked)
// g_A[row] = (in[row] @ W[K,64]) * dinv[row]     (A' form)
// in = X if SRC_EXT else relu(g_B + bias) applied during tile staging.
template <int K, bool SRC_EXT>
__global__ void __launch_bounds__(256)
k_gemm(const float* __restrict__ X, const float* __restrict__ W,
       const float* __restrict__ bias, int N) {
    __shared__ float Ws[K * HF];
    __shared__ float Xs[BK * XSTR];
    __shared__ float bs[K];

    const int tid = threadIdx.x;
    {
        const float4* Wv = reinterpret_cast<const float4*>(W);
        float4* Wsv = reinterpret_cast<float4*>(Ws);
        for (int i = tid; i < K * HF / 4; i += 256) Wsv[i] = Wv[i];
        if (!SRC_EXT && tid < K) bs[tid] = bias[tid];
    }

    const int bm = blockIdx.x * BM;
    const int tc = tid & 15;
    const int tr = tid >> 4;

    const float* src = SRC_EXT ? X : (const float*)g_B;

    float acc[8][4];
#pragma unroll
    for (int i = 0; i < 8; i++)
#pragma unroll
        for (int j = 0; j < 4; j++) acc[i][j] = 0.0f;

    __syncthreads();

    for (int k0 = 0; k0 < K; k0 += BK) {
#pragma unroll
        for (int i = tid; i < BM * BK / 4; i += 256) {
            int row = i >> 2;
            int kq  = i & 3;
            int r   = bm + row;
            float4 v = make_float4(0.f, 0.f, 0.f, 0.f);
            if (r < N) {
                v = *reinterpret_cast<const float4*>(src + (size_t)r * K + k0 + kq * 4);
                if (!SRC_EXT) {
                    int kb = k0 + kq * 4;
                    v.x = fmaxf(v.x + bs[kb + 0], 0.0f);
                    v.y = fmaxf(v.y + bs[kb + 1], 0.0f);
                    v.z = fmaxf(v.z + bs[kb + 2], 0.0f);
                    v.w = fmaxf(v.w + bs[kb + 3], 0.0f);
                }
            }
            Xs[(kq * 4 + 0) * XSTR + row] = v.x;
            Xs[(kq * 4 + 1) * XSTR + row] = v.y;
            Xs[(kq * 4 + 2) * XSTR + row] = v.z;
            Xs[(kq * 4 + 3) * XSTR + row] = v.w;
        }
        __syncthreads();

#pragma unroll
        for (int kk = 0; kk < BK; kk++) {
            float4 xa = *reinterpret_cast<const float4*>(&Xs[kk * XSTR + tr * 8 + 0]);
            float4 xb = *reinterpret_cast<const float4*>(&Xs[kk * XSTR + tr * 8 + 4]);
            float4 wv = *reinterpret_cast<const float4*>(&Ws[(k0 + kk) * HF + tc * 4]);
            float xr[8] = {xa.x, xa.y, xa.z, xa.w, xb.x, xb.y, xb.z, xb.w};
#pragma unroll
            for (int i = 0; i < 8; i++) {
                acc[i][0] += xr[i] * wv.x;
                acc[i][1] += xr[i] * wv.y;
                acc[i][2] += xr[i] * wv.z;
                acc[i][3] += xr[i] * wv.w;
            }
        }
        __syncthreads();
    }

#pragma unroll
    for (int i = 0; i < 8; i++) {
        int r = bm + tr * 8 + i;
        if (r >= N) break;
        float di = g_dinv[r];
        float4 v = make_float4(acc[i][0] * di, acc[i][1] * di,
                               acc[i][2] * di, acc[i][3] * di);
        *reinterpret_cast<float4*>(g_A + (size_t)r * HF + tc * 4) = v;
    }
}

// ------------------------------------------------------------ CSR gather
// g_B[d,:] = dinv[d] * ( A'[d,:] + sum_{j in row d} A'[col[j],:] )
// Half-warp per dst row: 16 lanes x float4 = 64 floats. Uncoupled warps hide
// degree-variance latency (this is why it must NOT be fused into the GEMMs).
__global__ void k_gather(int N) {
    int gt   = blockIdx.x * blockDim.x + threadIdx.x;
    int warp = gt >> 5;
    int lane = gt & 31;
    int d = warp * 2 + (lane >> 4);
    if (d >= N) return;
    int sub = lane & 15;

    const float4* Ap = reinterpret_cast<const float4*>(g_A);
    int beg = __ldg(&g_rowptr[d]);
    int end = __ldg(&g_rowptr[d + 1]);

    float4 acc = Ap[(size_t)d * 16 + sub];   // self loop term

    int j = beg;
    for (; j + 1 < end; j += 2) {
        int s0 = __ldg(&g_col[j]);
        int s1 = __ldg(&g_col[j + 1]);
        float4 v0 = Ap[(size_t)s0 * 16 + sub];
        float4 v1 = Ap[(size_t)s1 * 16 + sub];
        acc.x += v0.x + v1.x;
        acc.y += v0.y + v1.y;
        acc.z += v0.z + v1.z;
        acc.w += v0.w + v1.w;
    }
    if (j < end) {
        int s = __ldg(&g_col[j]);
        float4 v = Ap[(size_t)s * 16 + sub];
        acc.x += v.x; acc.y += v.y; acc.z += v.z; acc.w += v.w;
    }

    float di = g_dinv[d];
    acc.x *= di; acc.y *= di; acc.z *= di; acc.w *= di;
    reinterpret_cast<float4*>(g_B)[(size_t)d * 16 + sub] = acc;
}

// ---------------------------------- tiled classifier: out = relu(B + b2) @ Wc + bc
__global__ void __launch_bounds__(192)
k_final(const float* __restrict__ b2, const float* __restrict__ Wc,
        const float* __restrict__ bc, float* __restrict__ out, int N) {
    __shared__ float Ws[HF * CFP];     // 64 x 48, zero-padded
    __shared__ float Xs[BK * XSTR];
    __shared__ float bs[HF];
    __shared__ float bcs[CFP];

    const int tid = threadIdx.x;
    for (int i = tid; i < HF * CFP; i += 192) {
        int k = i / CFP, c = i % CFP;
        Ws[i] = (c < CF) ? Wc[k * CF + c] : 0.0f;
    }
    if (tid < HF)  bs[tid]  = b2[tid];
    if (tid < CFP) bcs[tid] = (tid < CF) ? bc[tid] : 0.0f;

    const int bm = blockIdx.x * BM;
    const int tc = tid % 12;
    const int tr = tid / 12;

    float acc[8][4];
#pragma unroll
    for (int i = 0; i < 8; i++)
#pragma unroll
        for (int j = 0; j < 4; j++) acc[i][j] = 0.0f;

    __syncthreads();

    for (int k0 = 0; k0 < HF; k0 += BK) {
        for (int i = tid; i < BM * BK / 4; i += 192) {
            int row = i >> 2;
            int kq  = i & 3;
            int r   = bm + row;
            float4 v = make_float4(0.f, 0.f, 0.f, 0.f);
            if (r < N) {
                v = *reinterpret_cast<const float4*>(g_B + (size_t)r * HF + k0 + kq * 4);
                int kb = k0 + kq * 4;
                v.x = fmaxf(v.x + bs[kb + 0], 0.0f);
                v.y = fmaxf(v.y + bs[kb + 1], 0.0f);
                v.z = fmaxf(v.z + bs[kb + 2], 0.0f);
                v.w = fmaxf(v.w + bs[kb + 3], 0.0f);
            }
            Xs[(kq * 4 + 0) * XSTR + row] = v.x;
            Xs[(kq * 4 + 1) * XSTR + row] = v.y;
            Xs[(kq * 4 + 2) * XSTR + row] = v.z;
            Xs[(kq * 4 + 3) * XSTR + row] = v.w;
        }
        __syncthreads();

#pragma unroll
        for (int kk = 0; kk < BK; kk++) {
            float4 xa = *reinterpret_cast<const float4*>(&Xs[kk * XSTR + tr * 8 + 0]);
            float4 xb = *reinterpret_cast<const float4*>(&Xs[kk * XSTR + tr * 8 + 4]);
            float4 wv = *reinterpret_cast<const float4*>(&Ws[(k0 + kk) * CFP + tc * 4]);
            float xr[8] = {xa.x, xa.y, xa.z, xa.w, xb.x, xb.y, xb.z, xb.w};
#pragma unroll
            for (int i = 0; i < 8; i++) {
                acc[i][0] += xr[i] * wv.x;
                acc[i][1] += xr[i] * wv.y;
                acc[i][2] += xr[i] * wv.z;
                acc[i][3] += xr[i] * wv.w;
            }
        }
        __syncthreads();
    }

    if (tc * 4 < CF) {
#pragma unroll
        for (int i = 0; i < 8; i++) {
            int r = bm + tr * 8 + i;
            if (r >= N) break;
            float4 v = make_float4(acc[i][0] + bcs[tc * 4 + 0],
                                   acc[i][1] + bcs[tc * 4 + 1],
                                   acc[i][2] + bcs[tc * 4 + 2],
                                   acc[i][3] + bcs[tc * 4 + 3]);
            *reinterpret_cast<float4*>(out + (size_t)r * CF + tc * 4) = v;
        }
    }
}

// ------------------------------------------------------------------ launcher
extern "C" void kernel_launch(void* const* d_in, const int* in_sizes, int n_in,
                              void* d_out, int out_size) {
    const float* x  = (const float*)d_in[0];
    const int*   ei = (const int*)d_in[1];     // int32 (JAX x64-disabled)
    const float* W1 = (const float*)d_in[2];
    const float* b1 = (const float*)d_in[3];
    const float* W2 = (const float*)d_in[4];
    const float* b2 = (const float*)d_in[5];
    const float* Wc = (const float*)d_in[6];
    const float* bc = (const float*)d_in[7];
    float*       out = (float*)d_out;

    const int Hdim = in_sizes[3];             // 64
    const int Fin  = in_sizes[2] / Hdim;      // 128
    const int N    = in_sizes[0] / Fin;       // 100000
    const int E    = in_sizes[1] / 2;         // 1000000
    (void)Hdim; (void)n_in; (void)out_size;

    const int TPB = 256;
    int nBlk  = (N + TPB - 1) / TPB;
    int e4Blk = ((E + 3) / 4 + TPB - 1) / TPB;   // 4 edges/thread
    int gBlk  = (N + BM - 1) / BM;
    int sBlkA = (N + 1023) / 1024;               // 98
    long long gatThreads = (long long)((N + 1) / 2) * 32;
    int gatBlk = (int)((gatThreads + TPB - 1) / TPB);

    // CSR build (4 launches; g_cnt arrives zeroed, leaves zeroed)
    k_count<<<e4Blk, TPB>>>(ei, E);
    k_scanA<<<sBlkA, 256>>>(N);
    k_scanC_prep<<<nBlk, TPB>>>(N, E, sBlkA);
    k_fill<<<e4Blk, TPB>>>(ei, E);

    // layer 1: A' = (x@W1)*dinv ; B = gather(A')
    k_gemm<128, true><<<gBlk, TPB>>>(x, W1, nullptr, N);
    k_gather<<<gatBlk, TPB>>>(N);

    // layer 2: A' = (relu(B+b1)@W2)*dinv ; B = gather(A')
    k_gemm<64, false><<<gBlk, TPB>>>(nullptr, W2, b1, N);
    k_gather<<<gatBlk, TPB>>>(N);

    // classifier (tiled, fuses relu(B + b2))
    k_final<<<gBlk, 192>>>(b2, Wc, bc, out, N);
}